// round 6
// baseline (speedup 1.0000x reference)
#include <cuda_runtime.h>
#include <math.h>

#define F_ 4
#define E_ 8
#define B_ 4096
#define D_ 512
#define H_ 1024
#define O_ 512
#define FE_ (F_*E_)

typedef unsigned long long ull;

// Scratch (no cudaMalloc allowed): gate (pre-scaled by 1/F) and gated hidden activations.
__device__ __align__(16) float g_gate[F_ * B_ * E_];                 // 512 KB
__device__ __align__(16) float g_hidden[(size_t)FE_ * B_ * H_];      // 512 MB

// ---- packed fp32x2 helpers (Blackwell FFMA2: 2x fp32 FMA throughput) ----
__device__ __forceinline__ ull ffma2(ull a, ull b, ull c) {
    ull d;
    asm("fma.rn.f32x2 %0, %1, %2, %3;" : "=l"(d) : "l"(a), "l"(b), "l"(c));
    return d;
}
__device__ __forceinline__ ull pack2(float x) {
    ull r;
    asm("mov.b64 %0, {%1, %2};" : "=l"(r) : "f"(x), "f"(x));
    return r;
}
__device__ __forceinline__ float2 unpack2(ull v) {
    float2 r;
    asm("mov.b64 {%0, %1}, %2;" : "=f"(r.x), "=f"(r.y) : "l"(v));
    return r;
}

// ============================================================================
// Kernel 1: gate logits + softmax, pre-scaled by 1/F. One thread per (f, b).
// ============================================================================
__global__ void gate_kernel(const float* __restrict__ feat,
                            const float* __restrict__ Wg,
                            const float* __restrict__ bg)
{
    const int b = blockIdx.x * blockDim.x + threadIdx.x;
    const int f = blockIdx.y;
    const float* x  = feat + ((size_t)f * B_ + b) * D_;
    const float* wg = Wg + (size_t)f * D_ * E_;

    float acc[E_];
#pragma unroll
    for (int e = 0; e < E_; ++e) acc[e] = bg[f * E_ + e];

    for (int d0 = 0; d0 < D_; d0 += 4) {
        float4 xv = *(const float4*)(x + d0);
        float xa[4] = {xv.x, xv.y, xv.z, xv.w};
#pragma unroll
        for (int q = 0; q < 4; ++q) {
            const float4* w = (const float4*)(wg + (size_t)(d0 + q) * E_);
            float4 w0 = w[0], w1 = w[1];
            acc[0] = fmaf(xa[q], w0.x, acc[0]);
            acc[1] = fmaf(xa[q], w0.y, acc[1]);
            acc[2] = fmaf(xa[q], w0.z, acc[2]);
            acc[3] = fmaf(xa[q], w0.w, acc[3]);
            acc[4] = fmaf(xa[q], w1.x, acc[4]);
            acc[5] = fmaf(xa[q], w1.y, acc[5]);
            acc[6] = fmaf(xa[q], w1.z, acc[6]);
            acc[7] = fmaf(xa[q], w1.w, acc[7]);
        }
    }
    float mx = acc[0];
#pragma unroll
    for (int e = 1; e < E_; ++e) mx = fmaxf(mx, acc[e]);
    float s = 0.f;
#pragma unroll
    for (int e = 0; e < E_; ++e) { acc[e] = expf(acc[e] - mx); s += acc[e]; }
    const float inv = 1.f / (s * (float)F_);   // fold mean-over-F here
#pragma unroll
    for (int e = 0; e < E_; ++e)
        g_gate[((size_t)f * B_ + b) * E_ + e] = acc[e] * inv;
}

// ============================================================================
// Kernel 2: hidden = gate * relu(X @ W1 + b1), per (f,e) batch.
// 128x128 tile, BK=16, 256 threads, 8x8/thread, FFMA2, double-buffered smem.
// ============================================================================
__global__ __launch_bounds__(256, 2)
void hidden_kernel(const float* __restrict__ feat,
                   const float* __restrict__ W1,
                   const float* __restrict__ b1)
{
    const int fe = blockIdx.z;
    const int f = fe >> 3, e = fe & 7;
    const int m0 = blockIdx.y * 128;
    const int n0 = blockIdx.x * 128;

    const float* __restrict__ A  = feat + (size_t)f * (B_ * D_);           // [B,D]
    const float* __restrict__ Bg = W1 + (size_t)fe * (D_ * H_);            // [D,H]
    float* __restrict__ C = g_hidden + (size_t)fe * ((size_t)B_ * H_);     // [B,H]

    __shared__ float As[2][16][132];   // transposed: As[k][m], +4 pad
    __shared__ float Bs[2][16][128];   // Bs[k][n]

    const int tid = threadIdx.x;
    const int tx = tid & 15;   // n-thread (split cols: tx*4 and 64+tx*4)
    const int ty = tid >> 4;   // m-thread (split rows: ty*4 and 64+ty*4)

    const int a_row = tid >> 2;            // 0..63 (and +64)
    const int a_c4  = (tid & 3) << 2;      // k offset within tile
    const int b_row = tid >> 5;            // 0..7 (and +8)
    const int b_c4  = (tid & 31) << 2;     // n offset

    ull acc[8][4];
#pragma unroll
    for (int i = 0; i < 8; ++i)
#pragma unroll
        for (int j = 0; j < 4; ++j) acc[i][j] = 0ull;

    float4 ar0, ar1, br0, br1;

    auto ldg_tile = [&](int k0) {
        const float* pa = A + (size_t)(m0 + a_row) * D_ + k0 + a_c4;
        ar0 = *(const float4*)pa;
        ar1 = *(const float4*)(pa + (size_t)64 * D_);
        const float* pb = Bg + (size_t)(k0 + b_row) * H_ + n0 + b_c4;
        br0 = *(const float4*)pb;
        br1 = *(const float4*)(pb + (size_t)8 * H_);
    };
    auto sts_tile = [&](int buf) {
        As[buf][a_c4 + 0][a_row] = ar0.x;
        As[buf][a_c4 + 1][a_row] = ar0.y;
        As[buf][a_c4 + 2][a_row] = ar0.z;
        As[buf][a_c4 + 3][a_row] = ar0.w;
        As[buf][a_c4 + 0][a_row + 64] = ar1.x;
        As[buf][a_c4 + 1][a_row + 64] = ar1.y;
        As[buf][a_c4 + 2][a_row + 64] = ar1.z;
        As[buf][a_c4 + 3][a_row + 64] = ar1.w;
        *(float4*)&Bs[buf][b_row][b_c4] = br0;
        *(float4*)&Bs[buf][b_row + 8][b_c4] = br1;
    };

    ldg_tile(0);
    sts_tile(0);

    const int KT = D_ / 16;  // 32
    for (int t = 0; t < KT; ++t) {
        __syncthreads();
        if (t + 1 < KT) ldg_tile((t + 1) * 16);
        const int cur = t & 1;
#pragma unroll
        for (int k = 0; k < 16; ++k) {
            float4 a0 = *(const float4*)&As[cur][k][ty * 4];
            float4 a1 = *(const float4*)&As[cur][k][64 + ty * 4];
            ulonglong2 bb0 = *(const ulonglong2*)&Bs[cur][k][tx * 4];
            ulonglong2 bb1 = *(const ulonglong2*)&Bs[cur][k][64 + tx * 4];
            float af[8] = {a0.x, a0.y, a0.z, a0.w, a1.x, a1.y, a1.z, a1.w};
            ull bv[4] = {bb0.x, bb0.y, bb1.x, bb1.y};
#pragma unroll
            for (int mi = 0; mi < 8; ++mi) {
                ull am = pack2(af[mi]);
#pragma unroll
                for (int j = 0; j < 4; ++j)
                    acc[mi][j] = ffma2(am, bv[j], acc[mi][j]);
            }
        }
        if (t + 1 < KT) sts_tile((t + 1) & 1);
    }

    // Epilogue: + b1, relu, * gate(1/F-scaled), store to g_hidden
    float4 b1a = *(const float4*)(b1 + (size_t)fe * H_ + n0 + tx * 4);
    float4 b1b = *(const float4*)(b1 + (size_t)fe * H_ + n0 + 64 + tx * 4);
    float b1v[8] = {b1a.x, b1a.y, b1a.z, b1a.w, b1b.x, b1b.y, b1b.z, b1b.w};

#pragma unroll
    for (int mi = 0; mi < 8; ++mi) {
        const int m = m0 + ((mi < 4) ? (ty * 4 + mi) : (64 + ty * 4 + mi - 4));
        const float g = g_gate[((size_t)f * B_ + m) * E_ + e];
        float v[8];
#pragma unroll
        for (int j = 0; j < 4; ++j) {
            float2 p = unpack2(acc[mi][j]);
            v[2 * j] = p.x; v[2 * j + 1] = p.y;
        }
        float4 o0, o1;
        o0.x = fmaxf(v[0] + b1v[0], 0.f) * g;
        o0.y = fmaxf(v[1] + b1v[1], 0.f) * g;
        o0.z = fmaxf(v[2] + b1v[2], 0.f) * g;
        o0.w = fmaxf(v[3] + b1v[3], 0.f) * g;
        o1.x = fmaxf(v[4] + b1v[4], 0.f) * g;
        o1.y = fmaxf(v[5] + b1v[5], 0.f) * g;
        o1.z = fmaxf(v[6] + b1v[6], 0.f) * g;
        o1.w = fmaxf(v[7] + b1v[7], 0.f) * g;
        *(float4*)&C[(size_t)m * H_ + n0 + tx * 4] = o0;
        *(float4*)&C[(size_t)m * H_ + n0 + 64 + tx * 4] = o1;
    }
}

// ============================================================================
// Kernel 3: out[b,o] = sum_{fe,k} h'[fe,b,k]*W2[fe,k,o] + sum_fe gate*b2.
// One GEMM with K = 32*1024 = 32768. 128x64 tile, 128 threads, 8x8/thread.
// ============================================================================
__global__ __launch_bounds__(128, 2)
void out_kernel(const float* __restrict__ W2,
                const float* __restrict__ b2,
                float* __restrict__ out)
{
    const int m0 = blockIdx.y * 128;
    const int n0 = blockIdx.x * 64;

    __shared__ float As[2][16][132];
    __shared__ float Bs[2][16][64];

    const int tid = threadIdx.x;
    const int tx = tid & 7;    // n: cols tx*4 and 32+tx*4
    const int ty = tid >> 3;   // m: rows ty*4 and 64+ty*4

    const int a_row = tid >> 2;          // 0..31 (+32*j)
    const int a_c4  = (tid & 3) << 2;
    const int b_row = tid >> 4;          // 0..7 (+8)
    const int b_c4  = (tid & 15) << 2;   // 0..60

    ull acc[8][4];
#pragma unroll
    for (int i = 0; i < 8; ++i)
#pragma unroll
        for (int j = 0; j < 4; ++j) acc[i][j] = 0ull;

    float4 ar[4], br0, br1;

    auto ldg_tile = [&](int t) {
        const int fe = t >> 6;            // H_/16 = 64 k-tiles per fe
        const int k0 = (t & 63) << 4;
        const float* pa = g_hidden + ((size_t)fe * B_ + m0 + a_row) * H_ + k0 + a_c4;
#pragma unroll
        for (int j = 0; j < 4; ++j)
            ar[j] = *(const float4*)(pa + (size_t)(32 * j) * H_);
        const float* pb = W2 + ((size_t)fe * H_ + k0 + b_row) * O_ + n0 + b_c4;
        br0 = *(const float4*)pb;
        br1 = *(const float4*)(pb + (size_t)8 * O_);
    };
    auto sts_tile = [&](int buf) {
#pragma unroll
        for (int j = 0; j < 4; ++j) {
            As[buf][a_c4 + 0][a_row + 32 * j] = ar[j].x;
            As[buf][a_c4 + 1][a_row + 32 * j] = ar[j].y;
            As[buf][a_c4 + 2][a_row + 32 * j] = ar[j].z;
            As[buf][a_c4 + 3][a_row + 32 * j] = ar[j].w;
        }
        *(float4*)&Bs[buf][b_row][b_c4] = br0;
        *(float4*)&Bs[buf][b_row + 8][b_c4] = br1;
    };

    ldg_tile(0);
    sts_tile(0);

    const int NT = FE_ * (H_ / 16);   // 2048
    for (int t = 0; t < NT; ++t) {
        __syncthreads();
        if (t + 1 < NT) ldg_tile(t + 1);
        const int cur = t & 1;
#pragma unroll
        for (int k = 0; k < 16; ++k) {
            float4 a0 = *(const float4*)&As[cur][k][ty * 4];
            float4 a1 = *(const float4*)&As[cur][k][64 + ty * 4];
            ulonglong2 bb0 = *(const ulonglong2*)&Bs[cur][k][tx * 4];
            ulonglong2 bb1 = *(const ulonglong2*)&Bs[cur][k][32 + tx * 4];
            float af[8] = {a0.x, a0.y, a0.z, a0.w, a1.x, a1.y, a1.z, a1.w};
            ull bv[4] = {bb0.x, bb0.y, bb1.x, bb1.y};
#pragma unroll
            for (int mi = 0; mi < 8; ++mi) {
                ull am = pack2(af[mi]);
#pragma unroll
                for (int j = 0; j < 4; ++j)
                    acc[mi][j] = ffma2(am, bv[j], acc[mi][j]);
            }
        }
        if (t + 1 < NT) sts_tile((t + 1) & 1);
    }

    // Epilogue: add sum_fe gate(f,m,e)/F * b2(fe,o) and store.
    const int c0 = n0 + tx * 4;
    const int c1 = n0 + 32 + tx * 4;
#pragma unroll
    for (int mi = 0; mi < 8; ++mi) {
        const int m = m0 + ((mi < 4) ? (ty * 4 + mi) : (64 + ty * 4 + mi - 4));
        float v[8];
#pragma unroll
        for (int j = 0; j < 4; ++j) {
            float2 p = unpack2(acc[mi][j]);
            v[2 * j] = p.x; v[2 * j + 1] = p.y;
        }
        float bias[8] = {0.f, 0.f, 0.f, 0.f, 0.f, 0.f, 0.f, 0.f};
#pragma unroll 4
        for (int fe = 0; fe < FE_; ++fe) {
            const float g = g_gate[((size_t)(fe >> 3) * B_ + m) * E_ + (fe & 7)];
            const float4 bb0 = *(const float4*)(b2 + (size_t)fe * O_ + c0);
            const float4 bb1 = *(const float4*)(b2 + (size_t)fe * O_ + c1);
            bias[0] = fmaf(g, bb0.x, bias[0]);
            bias[1] = fmaf(g, bb0.y, bias[1]);
            bias[2] = fmaf(g, bb0.z, bias[2]);
            bias[3] = fmaf(g, bb0.w, bias[3]);
            bias[4] = fmaf(g, bb1.x, bias[4]);
            bias[5] = fmaf(g, bb1.y, bias[5]);
            bias[6] = fmaf(g, bb1.z, bias[6]);
            bias[7] = fmaf(g, bb1.w, bias[7]);
        }
        float4 o0 = {v[0] + bias[0], v[1] + bias[1], v[2] + bias[2], v[3] + bias[3]};
        float4 o1 = {v[4] + bias[4], v[5] + bias[5], v[6] + bias[6], v[7] + bias[7]};
        *(float4*)&out[(size_t)m * O_ + c0] = o0;
        *(float4*)&out[(size_t)m * O_ + c1] = o1;
    }
}

// ============================================================================
extern "C" void kernel_launch(void* const* d_in, const int* in_sizes, int n_in,
                              void* d_out, int out_size)
{
    const float* feat = (const float*)d_in[0];   // [F,B,D]
    const float* W1   = (const float*)d_in[1];   // [F,E,D,H]
    const float* b1   = (const float*)d_in[2];   // [F,E,H]
    const float* W2   = (const float*)d_in[3];   // [F,E,H,O]
    const float* b2   = (const float*)d_in[4];   // [F,E,O]
    const float* Wg   = (const float*)d_in[5];   // [F,D,E]
    const float* bg   = (const float*)d_in[6];   // [F,E]
    float* out = (float*)d_out;                  // [B,O]

    gate_kernel<<<dim3(B_ / 256, F_), 256>>>(feat, Wg, bg);
    hidden_kernel<<<dim3(H_ / 128, B_ / 128, FE_), 256>>>(feat, W1, b1);
    out_kernel<<<dim3(O_ / 64, B_ / 128), 128>>>(W2, b2, out);
}

// round 7
// speedup vs baseline: 1.0018x; 1.0018x over previous
#include <cuda_runtime.h>
#include <math.h>

#define F_ 4
#define E_ 8
#define B_ 4096
#define D_ 512
#define H_ 1024
#define O_ 512
#define FE_ (F_*E_)

typedef unsigned long long ull;

// Scratch (no cudaMalloc allowed): gate (pre-scaled by 1/F) and gated hidden activations.
__device__ __align__(16) float g_gate[F_ * B_ * E_];                 // 512 KB
__device__ __align__(16) float g_hidden[(size_t)FE_ * B_ * H_];      // 512 MB

// ---- packed fp32x2 helpers (Blackwell FFMA2: 2x fp32 FMA throughput) ----
__device__ __forceinline__ ull ffma2(ull a, ull b, ull c) {
    ull d;
    asm("fma.rn.f32x2 %0, %1, %2, %3;" : "=l"(d) : "l"(a), "l"(b), "l"(c));
    return d;
}
__device__ __forceinline__ ull pack2(float x) {
    ull r;
    asm("mov.b64 %0, {%1, %2};" : "=l"(r) : "f"(x), "f"(x));
    return r;
}
__device__ __forceinline__ float2 unpack2(ull v) {
    float2 r;
    asm("mov.b64 {%0, %1}, %2;" : "=f"(r.x), "=f"(r.y) : "l"(v));
    return r;
}

// ============================================================================
// Kernel 1: gate logits + softmax, pre-scaled by 1/F. One thread per (f, b).
// ============================================================================
__global__ void gate_kernel(const float* __restrict__ feat,
                            const float* __restrict__ Wg,
                            const float* __restrict__ bg)
{
    const int b = blockIdx.x * blockDim.x + threadIdx.x;
    const int f = blockIdx.y;
    const float* x  = feat + ((size_t)f * B_ + b) * D_;
    const float* wg = Wg + (size_t)f * D_ * E_;

    float acc[E_];
#pragma unroll
    for (int e = 0; e < E_; ++e) acc[e] = bg[f * E_ + e];

    for (int d0 = 0; d0 < D_; d0 += 4) {
        float4 xv = *(const float4*)(x + d0);
        float xa[4] = {xv.x, xv.y, xv.z, xv.w};
#pragma unroll
        for (int q = 0; q < 4; ++q) {
            const float4* w = (const float4*)(wg + (size_t)(d0 + q) * E_);
            float4 w0 = w[0], w1 = w[1];
            acc[0] = fmaf(xa[q], w0.x, acc[0]);
            acc[1] = fmaf(xa[q], w0.y, acc[1]);
            acc[2] = fmaf(xa[q], w0.z, acc[2]);
            acc[3] = fmaf(xa[q], w0.w, acc[3]);
            acc[4] = fmaf(xa[q], w1.x, acc[4]);
            acc[5] = fmaf(xa[q], w1.y, acc[5]);
            acc[6] = fmaf(xa[q], w1.z, acc[6]);
            acc[7] = fmaf(xa[q], w1.w, acc[7]);
        }
    }
    float mx = acc[0];
#pragma unroll
    for (int e = 1; e < E_; ++e) mx = fmaxf(mx, acc[e]);
    float s = 0.f;
#pragma unroll
    for (int e = 0; e < E_; ++e) { acc[e] = expf(acc[e] - mx); s += acc[e]; }
    const float inv = 1.f / (s * (float)F_);   // fold mean-over-F here
#pragma unroll
    for (int e = 0; e < E_; ++e)
        g_gate[((size_t)f * B_ + b) * E_ + e] = acc[e] * inv;
}

// ============================================================================
// Kernel 2: hidden = gate * relu(X @ W1 + b1), per (f,e) batch.
// 128x128 tile, BK=16, 256 threads, 8x8/thread, FFMA2, double-buffered smem.
// ============================================================================
__global__ __launch_bounds__(256, 2)
void hidden_kernel(const float* __restrict__ feat,
                   const float* __restrict__ W1,
                   const float* __restrict__ b1)
{
    const int fe = blockIdx.z;
    const int f = fe >> 3, e = fe & 7;
    const int m0 = blockIdx.y * 128;
    const int n0 = blockIdx.x * 128;

    const float* __restrict__ A  = feat + (size_t)f * (B_ * D_);           // [B,D]
    const float* __restrict__ Bg = W1 + (size_t)fe * (D_ * H_);            // [D,H]
    float* __restrict__ C = g_hidden + (size_t)fe * ((size_t)B_ * H_);     // [B,H]

    __shared__ float As[2][16][132];   // transposed: As[k][m], +4 pad
    __shared__ float Bs[2][16][128];   // Bs[k][n]

    const int tid = threadIdx.x;
    const int tx = tid & 15;   // n-thread (split cols: tx*4 and 64+tx*4)
    const int ty = tid >> 4;   // m-thread (split rows: ty*4 and 64+ty*4)

    const int a_row = tid >> 2;            // 0..63 (and +64)
    const int a_c4  = (tid & 3) << 2;      // k offset within tile
    const int b_row = tid >> 5;            // 0..7 (and +8)
    const int b_c4  = (tid & 31) << 2;     // n offset

    ull acc[8][4];
#pragma unroll
    for (int i = 0; i < 8; ++i)
#pragma unroll
        for (int j = 0; j < 4; ++j) acc[i][j] = 0ull;

    float4 ar0, ar1, br0, br1;

    auto ldg_tile = [&](int k0) {
        const float* pa = A + (size_t)(m0 + a_row) * D_ + k0 + a_c4;
        ar0 = *(const float4*)pa;
        ar1 = *(const float4*)(pa + (size_t)64 * D_);
        const float* pb = Bg + (size_t)(k0 + b_row) * H_ + n0 + b_c4;
        br0 = *(const float4*)pb;
        br1 = *(const float4*)(pb + (size_t)8 * H_);
    };
    auto sts_tile = [&](int buf) {
        As[buf][a_c4 + 0][a_row] = ar0.x;
        As[buf][a_c4 + 1][a_row] = ar0.y;
        As[buf][a_c4 + 2][a_row] = ar0.z;
        As[buf][a_c4 + 3][a_row] = ar0.w;
        As[buf][a_c4 + 0][a_row + 64] = ar1.x;
        As[buf][a_c4 + 1][a_row + 64] = ar1.y;
        As[buf][a_c4 + 2][a_row + 64] = ar1.z;
        As[buf][a_c4 + 3][a_row + 64] = ar1.w;
        *(float4*)&Bs[buf][b_row][b_c4] = br0;
        *(float4*)&Bs[buf][b_row + 8][b_c4] = br1;
    };

    ldg_tile(0);
    sts_tile(0);

    const int KT = D_ / 16;  // 32
    for (int t = 0; t < KT; ++t) {
        __syncthreads();
        if (t + 1 < KT) ldg_tile((t + 1) * 16);
        const int cur = t & 1;
#pragma unroll
        for (int k = 0; k < 16; ++k) {
            float4 a0 = *(const float4*)&As[cur][k][ty * 4];
            float4 a1 = *(const float4*)&As[cur][k][64 + ty * 4];
            ulonglong2 bb0 = *(const ulonglong2*)&Bs[cur][k][tx * 4];
            ulonglong2 bb1 = *(const ulonglong2*)&Bs[cur][k][64 + tx * 4];
            float af[8] = {a0.x, a0.y, a0.z, a0.w, a1.x, a1.y, a1.z, a1.w};
            ull bv[4] = {bb0.x, bb0.y, bb1.x, bb1.y};
#pragma unroll
            for (int mi = 0; mi < 8; ++mi) {
                ull am = pack2(af[mi]);
#pragma unroll
                for (int j = 0; j < 4; ++j)
                    acc[mi][j] = ffma2(am, bv[j], acc[mi][j]);
            }
        }
        if (t + 1 < KT) sts_tile((t + 1) & 1);
    }

    // Epilogue: + b1, relu, * gate(1/F-scaled), store to g_hidden
    float4 b1a = *(const float4*)(b1 + (size_t)fe * H_ + n0 + tx * 4);
    float4 b1b = *(const float4*)(b1 + (size_t)fe * H_ + n0 + 64 + tx * 4);
    float b1v[8] = {b1a.x, b1a.y, b1a.z, b1a.w, b1b.x, b1b.y, b1b.z, b1b.w};

#pragma unroll
    for (int mi = 0; mi < 8; ++mi) {
        const int m = m0 + ((mi < 4) ? (ty * 4 + mi) : (64 + ty * 4 + mi - 4));
        const float g = g_gate[((size_t)f * B_ + m) * E_ + e];
        float v[8];
#pragma unroll
        for (int j = 0; j < 4; ++j) {
            float2 p = unpack2(acc[mi][j]);
            v[2 * j] = p.x; v[2 * j + 1] = p.y;
        }
        float4 o0, o1;
        o0.x = fmaxf(v[0] + b1v[0], 0.f) * g;
        o0.y = fmaxf(v[1] + b1v[1], 0.f) * g;
        o0.z = fmaxf(v[2] + b1v[2], 0.f) * g;
        o0.w = fmaxf(v[3] + b1v[3], 0.f) * g;
        o1.x = fmaxf(v[4] + b1v[4], 0.f) * g;
        o1.y = fmaxf(v[5] + b1v[5], 0.f) * g;
        o1.z = fmaxf(v[6] + b1v[6], 0.f) * g;
        o1.w = fmaxf(v[7] + b1v[7], 0.f) * g;
        *(float4*)&C[(size_t)m * H_ + n0 + tx * 4] = o0;
        *(float4*)&C[(size_t)m * H_ + n0 + 64 + tx * 4] = o1;
    }
}

// ============================================================================
// Kernel 3: out[b,o] = sum_{fe,k} h'[fe,b,k]*W2[fe,k,o] + sum_fe gate*b2.
// One GEMM with K = 32*1024 = 32768. 128x64 tile, 128 threads, 8x8/thread.
// ============================================================================
__global__ __launch_bounds__(128, 2)
void out_kernel(const float* __restrict__ W2,
                const float* __restrict__ b2,
                float* __restrict__ out)
{
    const int m0 = blockIdx.y * 128;
    const int n0 = blockIdx.x * 64;

    __shared__ float As[2][16][132];
    __shared__ float Bs[2][16][64];

    const int tid = threadIdx.x;
    const int tx = tid & 7;    // n: cols tx*4 and 32+tx*4
    const int ty = tid >> 3;   // m: rows ty*4 and 64+ty*4

    const int a_row = tid >> 2;          // 0..31 (+32*j)
    const int a_c4  = (tid & 3) << 2;
    const int b_row = tid >> 4;          // 0..7 (+8)
    const int b_c4  = (tid & 15) << 2;   // 0..60

    ull acc[8][4];
#pragma unroll
    for (int i = 0; i < 8; ++i)
#pragma unroll
        for (int j = 0; j < 4; ++j) acc[i][j] = 0ull;

    float4 ar[4], br0, br1;

    auto ldg_tile = [&](int t) {
        const int fe = t >> 6;            // H_/16 = 64 k-tiles per fe
        const int k0 = (t & 63) << 4;
        const float* pa = g_hidden + ((size_t)fe * B_ + m0 + a_row) * H_ + k0 + a_c4;
#pragma unroll
        for (int j = 0; j < 4; ++j)
            ar[j] = *(const float4*)(pa + (size_t)(32 * j) * H_);
        const float* pb = W2 + ((size_t)fe * H_ + k0 + b_row) * O_ + n0 + b_c4;
        br0 = *(const float4*)pb;
        br1 = *(const float4*)(pb + (size_t)8 * O_);
    };
    auto sts_tile = [&](int buf) {
#pragma unroll
        for (int j = 0; j < 4; ++j) {
            As[buf][a_c4 + 0][a_row + 32 * j] = ar[j].x;
            As[buf][a_c4 + 1][a_row + 32 * j] = ar[j].y;
            As[buf][a_c4 + 2][a_row + 32 * j] = ar[j].z;
            As[buf][a_c4 + 3][a_row + 32 * j] = ar[j].w;
        }
        *(float4*)&Bs[buf][b_row][b_c4] = br0;
        *(float4*)&Bs[buf][b_row + 8][b_c4] = br1;
    };

    ldg_tile(0);
    sts_tile(0);

    const int NT = FE_ * (H_ / 16);   // 2048
    for (int t = 0; t < NT; ++t) {
        __syncthreads();
        if (t + 1 < NT) ldg_tile(t + 1);
        const int cur = t & 1;
#pragma unroll
        for (int k = 0; k < 16; ++k) {
            float4 a0 = *(const float4*)&As[cur][k][ty * 4];
            float4 a1 = *(const float4*)&As[cur][k][64 + ty * 4];
            ulonglong2 bb0 = *(const ulonglong2*)&Bs[cur][k][tx * 4];
            ulonglong2 bb1 = *(const ulonglong2*)&Bs[cur][k][32 + tx * 4];
            float af[8] = {a0.x, a0.y, a0.z, a0.w, a1.x, a1.y, a1.z, a1.w};
            ull bv[4] = {bb0.x, bb0.y, bb1.x, bb1.y};
#pragma unroll
            for (int mi = 0; mi < 8; ++mi) {
                ull am = pack2(af[mi]);
#pragma unroll
                for (int j = 0; j < 4; ++j)
                    acc[mi][j] = ffma2(am, bv[j], acc[mi][j]);
            }
        }
        if (t + 1 < NT) sts_tile((t + 1) & 1);
    }

    // Epilogue: add sum_fe gate(f,m,e)/F * b2(fe,o) and store.
    const int c0 = n0 + tx * 4;
    const int c1 = n0 + 32 + tx * 4;
#pragma unroll
    for (int mi = 0; mi < 8; ++mi) {
        const int m = m0 + ((mi < 4) ? (ty * 4 + mi) : (64 + ty * 4 + mi - 4));
        float v[8];
#pragma unroll
        for (int j = 0; j < 4; ++j) {
            float2 p = unpack2(acc[mi][j]);
            v[2 * j] = p.x; v[2 * j + 1] = p.y;
        }
        float bias[8] = {0.f, 0.f, 0.f, 0.f, 0.f, 0.f, 0.f, 0.f};
#pragma unroll 4
        for (int fe = 0; fe < FE_; ++fe) {
            const float g = g_gate[((size_t)(fe >> 3) * B_ + m) * E_ + (fe & 7)];
            const float4 bb0 = *(const float4*)(b2 + (size_t)fe * O_ + c0);
            const float4 bb1 = *(const float4*)(b2 + (size_t)fe * O_ + c1);
            bias[0] = fmaf(g, bb0.x, bias[0]);
            bias[1] = fmaf(g, bb0.y, bias[1]);
            bias[2] = fmaf(g, bb0.z, bias[2]);
            bias[3] = fmaf(g, bb0.w, bias[3]);
            bias[4] = fmaf(g, bb1.x, bias[4]);
            bias[5] = fmaf(g, bb1.y, bias[5]);
            bias[6] = fmaf(g, bb1.z, bias[6]);
            bias[7] = fmaf(g, bb1.w, bias[7]);
        }
        float4 o0 = {v[0] + bias[0], v[1] + bias[1], v[2] + bias[2], v[3] + bias[3]};
        float4 o1 = {v[4] + bias[4], v[5] + bias[5], v[6] + bias[6], v[7] + bias[7]};
        *(float4*)&out[(size_t)m * O_ + c0] = o0;
        *(float4*)&out[(size_t)m * O_ + c1] = o1;
    }
}

// ============================================================================
extern "C" void kernel_launch(void* const* d_in, const int* in_sizes, int n_in,
                              void* d_out, int out_size)
{
    const float* feat = (const float*)d_in[0];   // [F,B,D]
    const float* W1   = (const float*)d_in[1];   // [F,E,D,H]
    const float* b1   = (const float*)d_in[2];   // [F,E,H]
    const float* W2   = (const float*)d_in[3];   // [F,E,H,O]
    const float* b2   = (const float*)d_in[4];   // [F,E,O]
    const float* Wg   = (const float*)d_in[5];   // [F,D,E]
    const float* bg   = (const float*)d_in[6];   // [F,E]
    float* out = (float*)d_out;                  // [B,O]

    gate_kernel<<<dim3(B_ / 256, F_), 256>>>(feat, Wg, bg);
    hidden_kernel<<<dim3(H_ / 128, B_ / 128, FE_), 256>>>(feat, W1, b1);
    out_kernel<<<dim3(O_ / 64, B_ / 128), 128>>>(W2, b2, out);
}